// round 9
// baseline (speedup 1.0000x reference)
#include <cuda_runtime.h>
#include <math.h>

#define NB 32
#define SDIM 256
#define SS 65536            // SDIM*SDIM
#define TOT (NB*SS)

#define T_FOV 0.08748866352592401f   // tan(10/360*pi)
#define EPSV 1e-7f
#define ONE_M_EPS 0.99999990f        // float(1.0 - 1e-7)
#define INV_GAMMA 0.45454545454545453f
#define GAMMA_F 2.2f
#define P1_STEPS 16                  // phase-1 step cap (2 branchless chunks of 8)
#define WSC (128.0f / T_FOV)         // pixel-projection scale

// Scratch (no allocations allowed)
static __device__ float g_params[NB * 8];   // la, lb, spec_alpha, spec_strength, ldx, ldy, ldz, eps^alpha
static __device__ int   g_min_bits[NB];     // min depth as positive-float bits
static __device__ float g_shadow[TOT];
static __device__ float4 g_quad[TOT];       // (v00, v01, v10, v11) border-clamped, 32MB
static __device__ int   g_queue[TOT];       // survivor ray indices
static __device__ int   g_qcount;

// Normalized 1D Gaussian weights (ksize=7, sigma=2); separable form of the
// reference's outer(g,g)/sum 2D kernel.
__constant__ float GW[7] = {0.07015933f, 0.13107488f, 0.19071282f,
                            0.21610594f,
                            0.19071282f, 0.13107488f, 0.07015933f};

__global__ void params_kernel(const float* __restrict__ netL,
                              const float* __restrict__ light) {
    int b = threadIdx.x;
    if (b == 0) g_qcount = 0;
    if (b >= NB) return;
    float t0 = tanhf(netL[b * 6 + 0]);
    float t1 = tanhf(netL[b * 6 + 1]);
    float t2 = tanhf(netL[b * 6 + 2]);
    float t5 = tanhf(netL[b * 6 + 5]);
    const float t_alpha = 10.313708498984761f;   // sqrt(128) - 1
    float sa = (t0 * 0.5f + 0.5f) * t_alpha + 1.0f;
    float spec_alpha = sa * sa;
    float* p = g_params + b * 8;
    p[0] = t1 * 0.5f + 0.5f;                  // light_a
    p[1] = t2 * 0.5f + 0.5f;                  // light_b
    p[2] = spec_alpha;                        // spec_alpha
    p[3] = (t5 * 0.5f + 0.5f) * 0.5f;         // spec_strength
    float lx = light[b * 2 + 0];
    float ly = light[b * 2 + 1];
    float n = sqrtf(lx * lx + ly * ly + 1.0f);
    p[4] = lx / n;
    p[5] = ly / n;
    p[6] = 1.0f / n;
    p[7] = __powf(EPSV, spec_alpha);          // spec_sh when spec clamps to EPS
    g_min_bits[b] = 0x7f7fffff;               // +FLT_MAX bits
}

// Build bilinear quad image + per-batch min-depth (positive-float atomicMin).
__global__ void __launch_bounds__(256) quad_kernel(const float* __restrict__ depth) {
    int idx = blockIdx.x * 256 + threadIdx.x;
    int b = idx >> 16;
    int p = idx & (SS - 1);
    int y = p >> 8;
    int x = p & 255;
    const float* dimg = depth + b * SS;
    int x1 = min(x + 1, 255);
    int y1 = min(y + 1, 255);
    float4 q;
    q.x = __ldg(dimg + y  * SDIM + x);
    q.y = __ldg(dimg + y  * SDIM + x1);
    q.z = __ldg(dimg + y1 * SDIM + x);
    q.w = __ldg(dimg + y1 * SDIM + x1);
    g_quad[idx] = q;

    float m = q.x;
    #pragma unroll
    for (int s = 16; s > 0; s >>= 1)
        m = fminf(m, __shfl_xor_sync(0xffffffffu, m, s));
    __shared__ float warp_min[8];
    if ((threadIdx.x & 31) == 0) warp_min[threadIdx.x >> 5] = m;
    __syncthreads();
    if (threadIdx.x == 0) {
        float bm = warp_min[0];
        #pragma unroll
        for (int w = 1; w < 8; w++) bm = fminf(bm, warp_min[w]);
        atomicMin(&g_min_bits[b], __float_as_int(bm));   // valid: all positive
    }
}

// 8 march steps kk = kb..kb+7 (no n-clamp: steps past n provably cannot
// produce a false hit — pzz < minz <= any sampled depth — and coords are
// NaN/overflow-safe via the [0,255] clamp). One RCP at the chunk center;
// rz via 3rd-order Horner (|e|<=0.02, trunc < 1.5e-7 rel).
__device__ __forceinline__ bool march8(float kb, float d,
                                       float sxW, float syW, float sz,
                                       float pxW0, float pyW0,
                                       const float4* __restrict__ quad) {
    float pzm = fmaf(kb + 3.5f, sz, d);
    float rzm = __fdividef(1.0f, pzm);
    float c = sz * rzm;
    bool hit = false;
    #pragma unroll
    for (int u = 0; u < 8; u++) {
        float kk = kb + (float)u;               // compile-time offset
        float e = ((float)u - 3.5f) * c;
        float t1 = 1.0f - e;
        float t2 = fmaf(-e, t1, 1.0f);
        float pl = fmaf(-e, t2, 1.0f);          // 1 - e + e^2 - e^3
        float rz = rzm * pl;
        float pzz = fmaf(kk, sz, d);
        float x = fmaf(fmaf(kk, sxW, pxW0), rz, 127.5f);
        float y = fmaf(fmaf(kk, syW, pyW0), rz, 127.5f);
        x = fminf(fmaxf(x, 0.0f), 255.0f);      // also maps NaN -> 0
        y = fminf(fmaxf(y, 0.0f), 255.0f);
        int x0i = __float2int_rd(x);
        int y0i = __float2int_rd(y);
        float wx = x - (float)x0i;
        float wy = y - (float)y0i;
        float4 q = __ldg(quad + y0i * SDIM + x0i);
        float top = fmaf(wx, q.y - q.x, q.x);
        float bot = fmaf(wx, q.w - q.z, q.z);
        float sampled = fmaf(wy, bot - top, top);
        hit |= (sampled < pzz);
    }
    return hit;
}

// Phase 1: branchless 16-step march (all 16 loads in flight), then one check.
// Survivors (no hit, n > 16) pushed to queue.
__global__ void __launch_bounds__(256) shadow1_kernel() {
    int idx = blockIdx.x * blockDim.x + threadIdx.x;
    int b = idx >> 16;
    int p = idx & (SS - 1);
    int i = p >> 8;
    int j = p & 255;

    const float4* quad = g_quad + b * SS;
    float d = __ldg(&g_quad[idx].x);            // quad.x == depth[p]

    float ci = __fmul_rn(__fadd_rn(__fmul_rn((float)i, 2.0f / 255.0f), -1.0f), T_FOV);
    float cj = __fmul_rn(__fadd_rn(__fmul_rn((float)j, 2.0f / 255.0f), -1.0f), T_FOV);

    const float* prm = g_params + b * 8;
    float sx = -prm[4] * (1.0f / 256.0f);
    float sy = -prm[5] * (1.0f / 256.0f);
    float sz = -prm[6] * (1.0f / 256.0f);       // strictly negative
    float sxW = sx * WSC, syW = sy * WSC;
    float pxW0 = cj * d * WSC, pyW0 = ci * d * WSC;
    float minz = __int_as_float(g_min_bits[b]) - 1e-5f;

    bool hit = march8(1.0f, d, sxW, syW, sz, pxW0, pyW0, quad);
    hit     |= march8(9.0f, d, sxW, syW, sz, pxW0, pyW0, quad);
    g_shadow[idx] = hit ? 1.0f : 0.0f;

    // Steps with pz >= minz: any bilinear sample is a convex combination of
    // depths >= min_depth, so shadow is impossible once pz < minz.
    float nf = fminf(floorf((d - minz) * __fdividef(-1.0f, sz)), 256.0f);

    bool surv = !hit && (nf > (float)P1_STEPS);
    unsigned mask = __ballot_sync(0xffffffffu, surv);
    if (mask) {
        int lane = threadIdx.x & 31;
        int leader = __ffs(mask) - 1;
        int base = 0;
        if (lane == leader) base = atomicAdd(&g_qcount, __popc(mask));
        base = __shfl_sync(0xffffffffu, base, leader);
        if (surv) g_queue[base + __popc(mask & ((1u << lane) - 1u))] = idx;
    }
}

// Phase 2: dense march of survivors from k = 17, exit check every 16 steps.
__global__ void __launch_bounds__(256) shadow2_kernel() {
    int total = g_qcount;
    for (int q = blockIdx.x * blockDim.x + threadIdx.x; q < total;
         q += gridDim.x * blockDim.x) {
        int idx = g_queue[q];
        int b = idx >> 16;
        int p = idx & (SS - 1);
        int i = p >> 8;
        int j = p & 255;

        const float4* quad = g_quad + b * SS;
        float d = __ldg(&g_quad[idx].x);

        float ci = __fmul_rn(__fadd_rn(__fmul_rn((float)i, 2.0f / 255.0f), -1.0f), T_FOV);
        float cj = __fmul_rn(__fadd_rn(__fmul_rn((float)j, 2.0f / 255.0f), -1.0f), T_FOV);

        const float* prm = g_params + b * 8;
        float sx = -prm[4] * (1.0f / 256.0f);
        float sy = -prm[5] * (1.0f / 256.0f);
        float sz = -prm[6] * (1.0f / 256.0f);
        float sxW = sx * WSC, syW = sy * WSC;
        float pxW0 = cj * d * WSC, pyW0 = ci * d * WSC;
        float minz = __int_as_float(g_min_bits[b]) - 1e-5f;

        float nf = fminf(floorf((d - minz) * __fdividef(-1.0f, sz)), 256.0f);

        bool hit = false;
        for (float kb = (float)(P1_STEPS + 1); kb <= nf && !hit; kb += 16.0f) {
            hit  = march8(kb,        d, sxW, syW, sz, pxW0, pyW0, quad);
            hit |= march8(kb + 8.0f, d, sxW, syW, sz, pxW0, pyW0, quad);
        }
        if (hit) g_shadow[idx] = 1.0f;
    }
}

// Fused: 7x7 separable Gaussian blur of shadow (smem tile) + Phong epilogue.
__global__ void __launch_bounds__(1024) final_kernel(const float* __restrict__ netA,
                                                     const float* __restrict__ normal,
                                                     float* __restrict__ out) {
    __shared__ float s_sh[38][40];
    __shared__ float s_hb[38][33];

    int b = blockIdx.z;
    int ti0 = blockIdx.y * 32;
    int tj0 = blockIdx.x * 32;
    int tx = threadIdx.x;
    int ty = threadIdx.y;
    int tid = ty * 32 + tx;

    const float* shb = g_shadow + b * SS;

    for (int t = tid; t < 38 * 38; t += 1024) {
        int r = t / 38;
        int c = t - r * 38;
        int gi = ti0 - 3 + r;
        int gj = tj0 - 3 + c;
        float v = 0.0f;
        if (gi >= 0 && gi < SDIM && gj >= 0 && gj < SDIM) v = shb[gi * SDIM + gj];
        s_sh[r][c] = v;
    }
    __syncthreads();

    for (int t = tid; t < 38 * 32; t += 1024) {
        int r = t >> 5;
        int c = t & 31;
        float acc = 0.0f;
        #pragma unroll
        for (int dj = 0; dj < 7; dj++) acc += GW[dj] * s_sh[r][c + dj];
        s_hb[r][c] = acc;
    }
    __syncthreads();

    float ssum = 0.0f;
    #pragma unroll
    for (int dy = 0; dy < 7; dy++) ssum += GW[dy] * s_hb[ty + dy][tx];
    float shadow_factor = fminf(fmaxf(1.0f - ssum, 0.1f), 1.0f);

    int i = ti0 + ty;
    int j = tj0 + tx;
    int p = i * SDIM + j;

    const float* prm = g_params + b * 8;
    float la = prm[0], lb = prm[1], spec_alpha = prm[2], spec_strength = prm[3];
    float ldx = prm[4], ldy = prm[5], ldz = prm[6], eps_pow = prm[7];

    const float* nb = normal + b * 3 * SS;
    float nx = __ldg(nb + p);
    float ny = __ldg(nb + SS + p);
    float nz = __ldg(nb + 2 * SS + p);

    float cosb = nx * ldx + ny * ldy + nz * ldz;
    float diffuse = fmaxf(cosb, 0.0f);

    float aj = __fmul_rn(__fadd_rn(__fmul_rn((float)(255 - j), 2.0f / 255.0f), -1.0f), T_FOV);
    float ai = __fmul_rn(__fadd_rn(__fmul_rn((float)(255 - i), 2.0f / 255.0f), -1.0f), T_FOV);
    float rnrm = rsqrtf(ai * ai + aj * aj + 1.0f);
    float vdx = aj * rnrm, vdy = ai * rnrm, vdz = rnrm;

    float rdx = 2.0f * cosb * nx - ldx;
    float rdy = 2.0f * cosb * ny - ldy;
    float rdz = 2.0f * cosb * nz - ldz;

    float mask = (i >= 5 && i < SDIM - 5 && j >= 5 && j < SDIM - 5) ? 1.0f : 0.0f;
    float spec = fmaxf(vdx * rdx + vdy * rdy + vdz * rdz, 0.0f)
               * ((cosb > 0.0f) ? 1.0f : 0.0f) * mask;
    float spec_sh = (spec > EPSV)
                  ? __powf(fminf(spec, ONE_M_EPS), spec_alpha)
                  : eps_pow;

    float shading = la + lb * diffuse * shadow_factor;
    float term2 = spec_strength * lb * spec_sh;

    const float NLOG2E2 = -2.8853900817779268f;   // -2*log2(e)
    const float* ab = netA + b * 5 * SS;
    float* ob = out + b * 3 * SS;
    #pragma unroll
    for (int c = 0; c < 3; c++) {
        float a = __ldg(ab + c * SS + p);
        float u = exp2f(a * NLOG2E2);
        float alb = exp2f(-GAMMA_F * __log2f(1.0f + u));
        float r = alb * shading + term2;
        ob[c * SS + p] = __powf(fmaxf(r, EPSV), INV_GAMMA);
    }
}

extern "C" void kernel_launch(void* const* d_in, const int* in_sizes, int n_in,
                              void* d_out, int out_size) {
    const float* netA   = (const float*)d_in[0];
    const float* netL   = (const float*)d_in[1];
    const float* normal = (const float*)d_in[2];
    const float* depth  = (const float*)d_in[3];
    const float* light  = (const float*)d_in[4];
    float* out = (float*)d_out;

    params_kernel<<<1, 32>>>(netL, light);
    quad_kernel<<<TOT / 256, 256>>>(depth);
    shadow1_kernel<<<TOT / 256, 256>>>();
    shadow2_kernel<<<1184, 256>>>();   // 8 blocks/SM * 148 SMs
    dim3 grid(SDIM / 32, SDIM / 32, NB);
    dim3 blk(32, 32);
    final_kernel<<<grid, blk>>>(netA, normal, out);
}